// round 16
// baseline (speedup 1.0000x reference)
#include <cuda_runtime.h>
#include <cuda_bf16.h>
#include <cstdint>
#include <mma.h>

using namespace nvcuda;

#define OMEGA 1.7f
typedef unsigned long long ull;

// ---------------- global scratch (allocations are forbidden) ----------------
__device__ float g_Mop[64 * 256];
__device__ float g_y0[4096 * 256];
__device__ __nv_bfloat16 g_xh[4096 * 128],  g_xl[4096 * 128];
__device__ __nv_bfloat16 g_h1h[4096 * 512], g_h1l[4096 * 512];
__device__ __nv_bfloat16 g_h2h[4096 * 512], g_h2l[4096 * 512];
__device__ __nv_bfloat16 g_w1h[128 * 512],  g_w1l[128 * 512];
__device__ __nv_bfloat16 g_w2h[512 * 512],  g_w2l[512 * 512];
__device__ __nv_bfloat16 g_w3h[512 * 512],  g_w3l[512 * 512];
__device__ __nv_bfloat16 g_w4h[512 * 256],  g_w4l[512 * 256];

__device__ __forceinline__ uint32_t pack_bf2(__nv_bfloat16 a, __nv_bfloat16 b) {
    return (uint32_t)__bfloat16_as_ushort(a) | ((uint32_t)__bfloat16_as_ushort(b) << 16);
}

// ---------------- split converts ----------------
__global__ void cvt_split(const float* __restrict__ in, __nv_bfloat16* __restrict__ hi,
                          __nv_bfloat16* __restrict__ lo, int n) {
    int i = blockIdx.x * 256 + threadIdx.x;
    if (i < n) {
        float v = in[i];
        __nv_bfloat16 h = __float2bfloat16(v);
        hi[i] = h;
        lo[i] = __float2bfloat16(v - __bfloat162float(h));
    }
}

// ---------------- setup: Mop = inv(A A^T) @ A ----------------
#define SETUP_SMEM ((64 * 260 + 64 * 130) * 4)
__global__ void setup_kernel(const float* __restrict__ A) {
    extern __shared__ float sm[];
    float* As = sm;
    float* G  = sm + 64 * 260;
    __shared__ float colp[64];
    const int tid = threadIdx.x;
    for (int i = tid; i < 64 * 64; i += 256) {
        int m = i >> 6, d = (i & 63) << 2;
        *(float4*)(As + m * 260 + d) = *(const float4*)(A + m * 256 + d);
    }
    __syncthreads();
    for (int o = tid; o < 64 * 64; o += 256) {
        int i = o >> 6, j = o & 63;
        const float4* ai = (const float4*)(As + i * 260);
        const float4* aj = (const float4*)(As + j * 260);
        float s = 0.f;
        #pragma unroll 8
        for (int d4 = 0; d4 < 64; d4++) {
            float4 a = ai[d4], b = aj[d4];
            s += a.x * b.x + a.y * b.y + a.z * b.z + a.w * b.w;
        }
        G[i * 130 + j] = s;
        G[i * 130 + 64 + j] = (i == j) ? 1.f : 0.f;
    }
    __syncthreads();
    for (int p = 0; p < 64; p++) {
        float pinv = 1.f / G[p * 130 + p];
        if (tid < 64) colp[tid] = G[tid * 130 + p];
        __syncthreads();
        if (tid < 128) G[p * 130 + tid] *= pinv;
        __syncthreads();
        for (int e = tid; e < 64 * 128; e += 256) {
            int i = e >> 7, c = e & 127;
            if (i != p) G[i * 130 + c] -= colp[i] * G[p * 130 + c];
        }
        __syncthreads();
    }
    for (int o = tid; o < 64 * 256; o += 256) {
        int m = o >> 8, d = o & 255;
        float s = 0.f;
        #pragma unroll 8
        for (int j = 0; j < 64; j++) s += G[m * 130 + 64 + j] * As[j * 260 + d];
        g_Mop[o] = s;
    }
}

// ---------------- wmma trunk GEMM v2 (unchanged from R15) ----------------
#define ALD 40
#define BLD2 136
#define ELD 36
#define GA_BUF (128 * ALD)
#define GB_BUF (32 * BLD2)
#define GO_AH 0
#define GO_AL (2 * GA_BUF * 2)
#define GO_BH (4 * GA_BUF * 2)
#define GO_BL (4 * GA_BUF * 2 + 2 * GB_BUF * 2)
#define GSMEM (4 * GA_BUF * 2 + 4 * GB_BUF * 2)

template <bool RELU, bool F32OUT>
__global__ __launch_bounds__(512, 1) void gemm_wmma2(
    const __nv_bfloat16* __restrict__ Ah, const __nv_bfloat16* __restrict__ Al,
    const __nv_bfloat16* __restrict__ Bh, const __nv_bfloat16* __restrict__ Bl,
    const float* __restrict__ bias, float* __restrict__ outf,
    __nv_bfloat16* __restrict__ outh, __nv_bfloat16* __restrict__ outl,
    int M, int N, int K) {
    extern __shared__ char smg[];
    __shared__ float sbias[128];
    __nv_bfloat16* As_h = (__nv_bfloat16*)(smg + GO_AH);
    __nv_bfloat16* As_l = (__nv_bfloat16*)(smg + GO_AL);
    __nv_bfloat16* Bs_h = (__nv_bfloat16*)(smg + GO_BH);
    __nv_bfloat16* Bs_l = (__nv_bfloat16*)(smg + GO_BL);
    float* ep = (float*)smg;

    const int tid = threadIdx.x, lane = tid & 31, wid = tid >> 5;
    const int wr = wid & 3, wc = wid >> 2;
    const int bm = blockIdx.y * 128, bn = blockIdx.x * 128;

    if (tid < 128) sbias[tid] = bias[bn + tid];

    wmma::fragment<wmma::accumulator, 16, 16, 16, float> acc[2][2];
    #pragma unroll
    for (int i = 0; i < 2; i++)
        #pragma unroll
        for (int j = 0; j < 2; j++) wmma::fill_fragment(acc[i][j], 0.f);

    const int arow = tid >> 2, aseg = (tid & 3) * 8;
    const int brow = tid >> 4, bseg = (tid & 15) * 8;

    const __nv_bfloat16* agh = Ah + (size_t)(bm + arow) * K + aseg;
    const __nv_bfloat16* agl = Al + (size_t)(bm + arow) * K + aseg;
    const __nv_bfloat16* bgh = Bh + (size_t)brow * N + bn + bseg;
    const __nv_bfloat16* bgl = Bl + (size_t)brow * N + bn + bseg;

    uint4 pah = *(const uint4*)(agh);
    uint4 pal = *(const uint4*)(agl);
    uint4 pbh = *(const uint4*)(bgh);
    uint4 pbl = *(const uint4*)(bgl);
    *(uint4*)(As_h + arow * ALD + aseg) = pah;
    *(uint4*)(As_l + arow * ALD + aseg) = pal;
    *(uint4*)(Bs_h + brow * BLD2 + bseg) = pbh;
    *(uint4*)(Bs_l + brow * BLD2 + bseg) = pbl;
    __syncthreads();

    const int nblk = K / 32;
    for (int blk = 0; blk < nblk; blk++) {
        int buf = blk & 1;
        if (blk + 1 < nblk) {
            pah = *(const uint4*)(agh + (blk + 1) * 32);
            pal = *(const uint4*)(agl + (blk + 1) * 32);
            pbh = *(const uint4*)(bgh + (size_t)(blk + 1) * 32 * N);
            pbl = *(const uint4*)(bgl + (size_t)(blk + 1) * 32 * N);
        }
        const __nv_bfloat16* ah_base = As_h + buf * GA_BUF;
        const __nv_bfloat16* al_base = As_l + buf * GA_BUF;
        const __nv_bfloat16* bh_base = Bs_h + buf * GB_BUF;
        const __nv_bfloat16* bl_base = Bs_l + buf * GB_BUF;

        #pragma unroll
        for (int kk = 0; kk < 32; kk += 16) {
            wmma::fragment<wmma::matrix_a, 16, 16, 16, __nv_bfloat16, wmma::row_major> afh[2], afl[2];
            wmma::fragment<wmma::matrix_b, 16, 16, 16, __nv_bfloat16, wmma::row_major> bfh[2], bfl[2];
            #pragma unroll
            for (int i = 0; i < 2; i++) {
                wmma::load_matrix_sync(afh[i], ah_base + (wr * 32 + i * 16) * ALD + kk, ALD);
                wmma::load_matrix_sync(afl[i], al_base + (wr * 32 + i * 16) * ALD + kk, ALD);
            }
            #pragma unroll
            for (int j = 0; j < 2; j++) {
                wmma::load_matrix_sync(bfh[j], bh_base + kk * BLD2 + wc * 32 + j * 16, BLD2);
                wmma::load_matrix_sync(bfl[j], bl_base + kk * BLD2 + wc * 32 + j * 16, BLD2);
            }
            #pragma unroll
            for (int i = 0; i < 2; i++)
                #pragma unroll
                for (int j = 0; j < 2; j++) {
                    wmma::mma_sync(acc[i][j], afh[i], bfh[j], acc[i][j]);
                    wmma::mma_sync(acc[i][j], afh[i], bfl[j], acc[i][j]);
                    wmma::mma_sync(acc[i][j], afl[i], bfh[j], acc[i][j]);
                }
        }

        if (blk + 1 < nblk) {
            int nb = buf ^ 1;
            *(uint4*)(As_h + nb * GA_BUF + arow * ALD + aseg) = pah;
            *(uint4*)(As_l + nb * GA_BUF + arow * ALD + aseg) = pal;
            *(uint4*)(Bs_h + nb * GB_BUF + brow * BLD2 + bseg) = pbh;
            *(uint4*)(Bs_l + nb * GB_BUF + brow * BLD2 + bseg) = pbl;
        }
        __syncthreads();
    }

    float* wep = ep + wid * 32 * ELD;
    #pragma unroll
    for (int i = 0; i < 2; i++)
        #pragma unroll
        for (int j = 0; j < 2; j++)
            wmma::store_matrix_sync(wep + i * 16 * ELD + j * 16, acc[i][j], ELD, wmma::mem_row_major);
    __syncwarp();

    const int grow = bm + wr * 32 + lane;
    const int gcol0 = bn + wc * 32;
    if (F32OUT) {
        float* op = outf + (size_t)grow * N + gcol0;
        #pragma unroll
        for (int c = 0; c < 32; c += 4) {
            float4 v = *(float4*)(wep + lane * ELD + c);
            v.x += sbias[wc * 32 + c + 0];
            v.y += sbias[wc * 32 + c + 1];
            v.z += sbias[wc * 32 + c + 2];
            v.w += sbias[wc * 32 + c + 3];
            if (RELU) {
                v.x = fmaxf(v.x, 0.f); v.y = fmaxf(v.y, 0.f);
                v.z = fmaxf(v.z, 0.f); v.w = fmaxf(v.w, 0.f);
            }
            *(float4*)(op + c) = v;
        }
    } else {
        uint32_t hp[16], lp[16];
        #pragma unroll
        for (int c = 0; c < 32; c += 2) {
            float v0 = wep[lane * ELD + c]     + sbias[wc * 32 + c];
            float v1 = wep[lane * ELD + c + 1] + sbias[wc * 32 + c + 1];
            if (RELU) { v0 = fmaxf(v0, 0.f); v1 = fmaxf(v1, 0.f); }
            __nv_bfloat16 h0 = __float2bfloat16(v0), h1 = __float2bfloat16(v1);
            __nv_bfloat16 l0 = __float2bfloat16(v0 - __bfloat162float(h0));
            __nv_bfloat16 l1 = __float2bfloat16(v1 - __bfloat162float(h1));
            hp[c >> 1] = pack_bf2(h0, h1);
            lp[c >> 1] = pack_bf2(l0, l1);
        }
        size_t g = (size_t)grow * N + gcol0;
        *(uint4*)(outh + g)      = make_uint4(hp[0],  hp[1],  hp[2],  hp[3]);
        *(uint4*)(outh + g + 8)  = make_uint4(hp[4],  hp[5],  hp[6],  hp[7]);
        *(uint4*)(outh + g + 16) = make_uint4(hp[8],  hp[9],  hp[10], hp[11]);
        *(uint4*)(outh + g + 24) = make_uint4(hp[12], hp[13], hp[14], hp[15]);
        *(uint4*)(outl + g)      = make_uint4(lp[0],  lp[1],  lp[2],  lp[3]);
        *(uint4*)(outl + g + 8)  = make_uint4(lp[4],  lp[5],  lp[6],  lp[7]);
        *(uint4*)(outl + g + 16) = make_uint4(lp[8],  lp[9],  lp[10], lp[11]);
        *(uint4*)(outl + g + 24) = make_uint4(lp[12], lp[13], lp[14], lp[15]);
    }
}

// ---------------- wmma iteration kernel: 512 threads, term-parallel accumulators ----------------
#define IT_BT_H 0
#define IT_BT_L 36864
#define IT_MO_H 73728
#define IT_MO_L 107520
#define IT_ZH   141312
#define IT_ZL   158208
#define IT_TH   175104
#define IT_TL   179712
#define IT_SC   184320
#define IT_SMEM 217600
#define ZB 264
#define TB 72
#define SB 260
#define SC1B_OFF 2304

__device__ __forceinline__ void it_gemm1(const __nv_bfloat16* zh, const __nv_bfloat16* zl,
                                         const __nv_bfloat16* Bh, const __nv_bfloat16* Bl,
                                         float* sc1, int tr, int tc, int kh) {
    // three independent accumulators (hi*hi, hi*lo, lo*hi) -> chains of 8, not 24
    wmma::fragment<wmma::accumulator, 16, 16, 16, float> a_hh, a_hl, a_lh;
    wmma::fill_fragment(a_hh, 0.f);
    wmma::fill_fragment(a_hl, 0.f);
    wmma::fill_fragment(a_lh, 0.f);
    #pragma unroll
    for (int k = 0; k < 8; k++) {
        int kk = kh * 8 + k;
        wmma::fragment<wmma::matrix_a, 16, 16, 16, __nv_bfloat16, wmma::row_major> ah, al;
        wmma::fragment<wmma::matrix_b, 16, 16, 16, __nv_bfloat16, wmma::row_major> bh, bl;
        wmma::load_matrix_sync(ah, zh + tr * 16 * ZB + kk * 16, ZB);
        wmma::load_matrix_sync(al, zl + tr * 16 * ZB + kk * 16, ZB);
        wmma::load_matrix_sync(bh, Bh + kk * 16 * TB + tc * 16, TB);
        wmma::load_matrix_sync(bl, Bl + kk * 16 * TB + tc * 16, TB);
        wmma::mma_sync(a_hh, ah, bh, a_hh);
        wmma::mma_sync(a_hl, ah, bl, a_hl);
        wmma::mma_sync(a_lh, al, bh, a_lh);
    }
    #pragma unroll
    for (int e = 0; e < a_hh.num_elements; e++)
        a_hh.x[e] += a_hl.x[e] + a_lh.x[e];
    wmma::store_matrix_sync(sc1 + tr * 16 * TB + tc * 16, a_hh, TB, wmma::mem_row_major);
}

__device__ __forceinline__ void it_gemm2(const __nv_bfloat16* th, const __nv_bfloat16* tl,
                                         const __nv_bfloat16* Mh, const __nv_bfloat16* Ml,
                                         float* scf, int tr, int tcol) {
    wmma::fragment<wmma::accumulator, 16, 16, 16, float> a_hh[2], a_hl[2], a_lh[2];
    #pragma unroll
    for (int j = 0; j < 2; j++) {
        wmma::fill_fragment(a_hh[j], 0.f);
        wmma::fill_fragment(a_hl[j], 0.f);
        wmma::fill_fragment(a_lh[j], 0.f);
    }
    #pragma unroll
    for (int k = 0; k < 4; k++) {
        wmma::fragment<wmma::matrix_a, 16, 16, 16, __nv_bfloat16, wmma::row_major> ah, al;
        wmma::load_matrix_sync(ah, th + tr * 16 * TB + k * 16, TB);
        wmma::load_matrix_sync(al, tl + tr * 16 * TB + k * 16, TB);
        #pragma unroll
        for (int j = 0; j < 2; j++) {
            wmma::fragment<wmma::matrix_b, 16, 16, 16, __nv_bfloat16, wmma::row_major> bh, bl;
            wmma::load_matrix_sync(bh, Mh + k * 16 * ZB + tcol * 32 + j * 16, ZB);
            wmma::load_matrix_sync(bl, Ml + k * 16 * ZB + tcol * 32 + j * 16, ZB);
            wmma::mma_sync(a_hh[j], ah, bh, a_hh[j]);
            wmma::mma_sync(a_hl[j], ah, bl, a_hl[j]);
            wmma::mma_sync(a_lh[j], al, bh, a_lh[j]);
        }
    }
    #pragma unroll
    for (int j = 0; j < 2; j++) {
        #pragma unroll
        for (int e = 0; e < a_hh[j].num_elements; e++)
            a_hh[j].x[e] += a_hl[j].x[e] + a_lh[j].x[e];
        wmma::store_matrix_sync(scf + tr * 16 * SB + tcol * 32 + j * 16, a_hh[j], SB, wmma::mem_row_major);
    }
}

__global__ __launch_bounds__(512, 1) void iter_wmma(
    const float* __restrict__ y0g, const float* __restrict__ bcong,
    const float* __restrict__ Ag, float* __restrict__ outg,
    const int* __restrict__ nip) {
    extern __shared__ char smi[];
    __nv_bfloat16* Bt_h = (__nv_bfloat16*)(smi + IT_BT_H);
    __nv_bfloat16* Bt_l = (__nv_bfloat16*)(smi + IT_BT_L);
    __nv_bfloat16* Mo_h = (__nv_bfloat16*)(smi + IT_MO_H);
    __nv_bfloat16* Mo_l = (__nv_bfloat16*)(smi + IT_MO_L);
    __nv_bfloat16* zh   = (__nv_bfloat16*)(smi + IT_ZH);
    __nv_bfloat16* zl   = (__nv_bfloat16*)(smi + IT_ZL);
    __nv_bfloat16* th   = (__nv_bfloat16*)(smi + IT_TH);
    __nv_bfloat16* tl   = (__nv_bfloat16*)(smi + IT_TL);
    float*         scf  = (float*)(smi + IT_SC);
    float*         sc1a = scf;
    float*         sc1b = scf + SC1B_OFF;

    const int tid = threadIdx.x, lane = tid & 31, w = tid >> 5;
    const int g1_tr = w & 1, g1_tc = (w >> 1) & 3, g1_kh = w >> 3;
    const int g2_tr = w & 1, g2_tc = w >> 1;
    const int row0 = blockIdx.x * 32;
    const int wc0 = w * 16;
    const int s_row = tid >> 4, s_m0 = (tid & 15) * 4;
    const int ni = *nip;

    for (int i = tid; i < 64 * 256; i += 512) {
        int m = i >> 8, d = i & 255;
        float v = 0.5f * Ag[i];
        __nv_bfloat16 h = __float2bfloat16(v);
        Bt_h[d * TB + m] = h;
        Bt_l[d * TB + m] = __float2bfloat16(v - __bfloat162float(h));
    }
    for (int i = tid; i < 64 * 256; i += 512) {
        int m = i >> 8, c = i & 255;
        float v = g_Mop[i];
        __nv_bfloat16 h = __float2bfloat16(v);
        Mo_h[m * ZB + c] = h;
        Mo_l[m * ZB + c] = __float2bfloat16(v - __bfloat162float(h));
    }
    float z[16], rv[16];
    #pragma unroll
    for (int j = 0; j < 16; j += 2) {
        float2 v = *(const float2*)(y0g + (size_t)(row0 + lane) * 256 + wc0 + j);
        z[j] = v.x; z[j + 1] = v.y;
        __nv_bfloat16 h0 = __float2bfloat16(v.x), h1 = __float2bfloat16(v.y);
        __nv_bfloat16 l0 = __float2bfloat16(v.x - __bfloat162float(h0));
        __nv_bfloat16 l1 = __float2bfloat16(v.y - __bfloat162float(h1));
        *(uint32_t*)(zh + lane * ZB + wc0 + j) = pack_bf2(h0, h1);
        *(uint32_t*)(zl + lane * ZB + wc0 + j) = pack_bf2(l0, l1);
    }
    __syncthreads();

    it_gemm1(zh, zl, Bt_h, Bt_l, g1_kh ? sc1b : sc1a, g1_tr, g1_tc, g1_kh);
    __syncthreads();
    {
        float4 va = *(const float4*)(sc1a + s_row * TB + s_m0);
        float4 vb = *(const float4*)(sc1b + s_row * TB + s_m0);
        const float* bp = bcong + (size_t)(row0 + s_row) * 64 + s_m0;
        float f[4] = {va.x + vb.x - bp[0], va.y + vb.y - bp[1],
                      va.z + vb.z - bp[2], va.w + vb.w - bp[3]};
        #pragma unroll
        for (int q = 0; q < 4; q += 2) {
            __nv_bfloat16 h0 = __float2bfloat16(f[q]), h1 = __float2bfloat16(f[q + 1]);
            __nv_bfloat16 l0 = __float2bfloat16(f[q]     - __bfloat162float(h0));
            __nv_bfloat16 l1 = __float2bfloat16(f[q + 1] - __bfloat162float(h1));
            *(uint32_t*)(th + s_row * TB + s_m0 + q) = pack_bf2(h0, h1);
            *(uint32_t*)(tl + s_row * TB + s_m0 + q) = pack_bf2(l0, l1);
        }
    }
    __syncthreads();
    it_gemm2(th, tl, Mo_h, Mo_l, scf, g2_tr, g2_tc);
    __syncthreads();
    #pragma unroll
    for (int j = 0; j < 16; j += 2) {
        float2 sv = *(const float2*)(scf + lane * SB + wc0 + j);
        rv[j]     = 0.5f * z[j]     - sv.x;
        rv[j + 1] = 0.5f * z[j + 1] - sv.y;
    }

    for (int it = 0; it < ni; it++) {
        __syncthreads();
        it_gemm1(zh, zl, Bt_h, Bt_l, g1_kh ? sc1b : sc1a, g1_tr, g1_tc, g1_kh);
        __syncthreads();
        {
            float4 va = *(const float4*)(sc1a + s_row * TB + s_m0);
            float4 vb = *(const float4*)(sc1b + s_row * TB + s_m0);
            float f[4] = {va.x + vb.x, va.y + vb.y, va.z + vb.z, va.w + vb.w};
            #pragma unroll
            for (int q = 0; q < 4; q += 2) {
                __nv_bfloat16 h0 = __float2bfloat16(f[q]), h1 = __float2bfloat16(f[q + 1]);
                __nv_bfloat16 l0 = __float2bfloat16(f[q]     - __bfloat162float(h0));
                __nv_bfloat16 l1 = __float2bfloat16(f[q + 1] - __bfloat162float(h1));
                *(uint32_t*)(th + s_row * TB + s_m0 + q) = pack_bf2(h0, h1);
                *(uint32_t*)(tl + s_row * TB + s_m0 + q) = pack_bf2(l0, l1);
            }
        }
        __syncthreads();
        it_gemm2(th, tl, Mo_h, Mo_l, scf, g2_tr, g2_tc);
        __syncthreads();
        if (it == ni - 1) {
            #pragma unroll
            for (int j = 0; j < 16; j += 2) {
                float2 sv = *(const float2*)(scf + lane * SB + wc0 + j);
                float y0v = 0.5f * z[j]     - sv.x + rv[j];
                float y1v = 0.5f * z[j + 1] - sv.y + rv[j + 1];
                *(float2*)(outg + (size_t)(row0 + lane) * 256 + wc0 + j) = make_float2(y0v, y1v);
            }
        } else {
            #pragma unroll
            for (int j = 0; j < 16; j += 2) {
                float2 sv = *(const float2*)(scf + lane * SB + wc0 + j);
                float y0v = 0.5f * z[j]     - sv.x + rv[j];
                float y1v = 0.5f * z[j + 1] - sv.y + rv[j + 1];
                float w0 = fmaxf(2.f * y0v - z[j],     0.f);
                float w1 = fmaxf(2.f * y1v - z[j + 1], 0.f);
                z[j]     += OMEGA * (w0 - y0v);
                z[j + 1] += OMEGA * (w1 - y1v);
                __nv_bfloat16 h0 = __float2bfloat16(z[j]), h1 = __float2bfloat16(z[j + 1]);
                __nv_bfloat16 l0 = __float2bfloat16(z[j]     - __bfloat162float(h0));
                __nv_bfloat16 l1 = __float2bfloat16(z[j + 1] - __bfloat162float(h1));
                *(uint32_t*)(zh + lane * ZB + wc0 + j) = pack_bf2(h0, h1);
                *(uint32_t*)(zl + lane * ZB + wc0 + j) = pack_bf2(l0, l1);
            }
        }
    }
}

// =====================================================================
extern "C" void kernel_launch(void* const* d_in, const int* in_sizes, int n_in,
                              void* d_out, int out_size) {
    const float* x    = (const float*)d_in[0];
    const float* bcon = (const float*)d_in[1];
    const float* A    = (const float*)d_in[2];
    const float* W1   = (const float*)d_in[3];
    const float* b1   = (const float*)d_in[4];
    const float* W2   = (const float*)d_in[5];
    const float* b2   = (const float*)d_in[6];
    const float* W3   = (const float*)d_in[7];
    const float* b3   = (const float*)d_in[8];
    const float* Wout = (const float*)d_in[9];
    const float* bout = (const float*)d_in[10];
    const int*   nip  = (const int*)d_in[11];
    float* out = (float*)d_out;

    cudaFuncSetAttribute(setup_kernel, cudaFuncAttributeMaxDynamicSharedMemorySize, SETUP_SMEM);
    cudaFuncSetAttribute(iter_wmma,    cudaFuncAttributeMaxDynamicSharedMemorySize, IT_SMEM);
    cudaFuncSetAttribute(gemm_wmma2<true, false>, cudaFuncAttributeMaxDynamicSharedMemorySize, GSMEM);
    cudaFuncSetAttribute(gemm_wmma2<false, true>, cudaFuncAttributeMaxDynamicSharedMemorySize, GSMEM);

    void *py0;
    cudaGetSymbolAddress(&py0, g_y0);
    float* y0 = (float*)py0;
    void *pxh, *pxl, *p1h, *p1l, *p2h, *p2l;
    void *pw1h, *pw1l, *pw2h, *pw2l, *pw3h, *pw3l, *pw4h, *pw4l;
    cudaGetSymbolAddress(&pxh, g_xh);   cudaGetSymbolAddress(&pxl, g_xl);
    cudaGetSymbolAddress(&p1h, g_h1h);  cudaGetSymbolAddress(&p1l, g_h1l);
    cudaGetSymbolAddress(&p2h, g_h2h);  cudaGetSymbolAddress(&p2l, g_h2l);
    cudaGetSymbolAddress(&pw1h, g_w1h); cudaGetSymbolAddress(&pw1l, g_w1l);
    cudaGetSymbolAddress(&pw2h, g_w2h); cudaGetSymbolAddress(&pw2l, g_w2l);
    cudaGetSymbolAddress(&pw3h, g_w3h); cudaGetSymbolAddress(&pw3l, g_w3l);
    cudaGetSymbolAddress(&pw4h, g_w4h); cudaGetSymbolAddress(&pw4l, g_w4l);
    __nv_bfloat16 *xh = (__nv_bfloat16*)pxh, *xl = (__nv_bfloat16*)pxl;
    __nv_bfloat16 *h1h = (__nv_bfloat16*)p1h, *h1l = (__nv_bfloat16*)p1l;
    __nv_bfloat16 *h2h = (__nv_bfloat16*)p2h, *h2l = (__nv_bfloat16*)p2l;
    __nv_bfloat16 *w1h = (__nv_bfloat16*)pw1h, *w1l = (__nv_bfloat16*)pw1l;
    __nv_bfloat16 *w2h = (__nv_bfloat16*)pw2h, *w2l = (__nv_bfloat16*)pw2l;
    __nv_bfloat16 *w3h = (__nv_bfloat16*)pw3h, *w3l = (__nv_bfloat16*)pw3l;
    __nv_bfloat16 *w4h = (__nv_bfloat16*)pw4h, *w4l = (__nv_bfloat16*)pw4l;

    cvt_split<<<(4096 * 128 + 255) / 256, 256>>>(x, xh, xl, 4096 * 128);
    cvt_split<<<(128 * 512 + 255) / 256, 256>>>(W1, w1h, w1l, 128 * 512);
    cvt_split<<<(512 * 512 + 255) / 256, 256>>>(W2, w2h, w2l, 512 * 512);
    cvt_split<<<(512 * 512 + 255) / 256, 256>>>(W3, w3h, w3l, 512 * 512);
    cvt_split<<<(512 * 256 + 255) / 256, 256>>>(Wout, w4h, w4l, 512 * 256);
    setup_kernel<<<1, 256, SETUP_SMEM>>>(A);

    gemm_wmma2<true, false><<<dim3(4, 32), 512, GSMEM>>>(xh, xl, w1h, w1l, b1, nullptr, h1h, h1l, 4096, 512, 128);
    gemm_wmma2<true, false><<<dim3(4, 32), 512, GSMEM>>>(h1h, h1l, w2h, w2l, b2, nullptr, h2h, h2l, 4096, 512, 512);
    gemm_wmma2<true, false><<<dim3(4, 32), 512, GSMEM>>>(h2h, h2l, w3h, w3l, b3, nullptr, h1h, h1l, 4096, 512, 512);
    gemm_wmma2<false, true><<<dim3(2, 32), 512, GSMEM>>>(h1h, h1l, w4h, w4l, bout, y0, nullptr, nullptr, 4096, 256, 512);

    iter_wmma<<<128, 512, IT_SMEM>>>(y0, bcon, A, out, nip);
}